// round 2
// baseline (speedup 1.0000x reference)
#include <cuda_runtime.h>
#include <cstddef>

#define N_    128
#define CIN   8
#define HIN   128
#define WIN   128
#define COUT  64
#define OH    126
#define OW    126
#define G_    16
#define CPG   4
#define OPH   31
#define OPW   31
#define WPAD  128
#define TH    8
#define TROWS (TH + 2)

typedef unsigned long long ull;

// Scratch: conv output, padded rows. 528 MB.
__device__ float g_y[(size_t)N_ * COUT * OH * WPAD];
__device__ float g_sum[N_ * G_];
__device__ float g_sqs[N_ * G_];
__device__ float g_mean[N_ * G_];
__device__ float g_rsig[N_ * G_];

// ---- packed f32x2 helpers -------------------------------------------------
__device__ __forceinline__ ull pk2(float lo, float hi) {
    ull r; asm("mov.b64 %0, {%1, %2};" : "=l"(r) : "f"(lo), "f"(hi)); return r;
}
__device__ __forceinline__ void fma2(ull& d, ull a, ull b) {
    asm("fma.rn.f32x2 %0, %1, %2, %0;" : "+l"(d) : "l"(a), "l"(b));
}
__device__ __forceinline__ ull add2(ull a, ull b) {
    ull r; asm("add.rn.f32x2 %0, %1, %2;" : "=l"(r) : "l"(a), "l"(b)); return r;
}
__device__ __forceinline__ void unpk(ull v, float& lo, float& hi) {
    asm("mov.b64 {%0, %1}, %2;" : "=f"(lo), "=f"(hi) : "l"(v));
}

// ---------------------------------------------------------------------------
// Kernel 1: conv(3x3, 8ic -> 4 oc of this group) + bias via packed FFMA2,
// scratch write, deterministic block reduction of sum/sumsq.
// One block per (group, n). 128 threads: row = tid>>4 (0..7), wt = tid&15,
// each thread produces 4 oc x 8 adjacent w (as 4 f32x2 pairs).
// ---------------------------------------------------------------------------
__global__ __launch_bounds__(128) void conv_stats_kernel(
    const float* __restrict__ x,
    const float* __restrict__ cw,
    const float* __restrict__ cb)
{
    __shared__ float4 s_in[CIN][TROWS][33];   // 42240 B (132 floats/row, last f4 zero)
    __shared__ ull    s_wp[CIN][3][12];       // packed (w,w) pairs: [ic][kh][oc*3+t]
    __shared__ float  s_bias[CPG];
    __shared__ float  s_red[256];

    const int g   = blockIdx.x;
    const int n   = blockIdx.y;
    const int tid = threadIdx.x;

    // Pre-duplicate weights into packed pairs (288 entries)
    for (int e = tid; e < 288; e += 128) {
        int t  = e % 3;
        int oc = (e / 3) & 3;
        int kh = (e / 12) % 3;
        int ic = e / 36;
        float w = cw[(((size_t)(g * CPG + oc) * CIN + ic) * 3 + kh) * 3 + t];
        s_wp[ic][kh][oc * 3 + t] = pk2(w, w);
    }
    if (tid < CPG) s_bias[tid] = cb[g * CPG + tid];

    const int row = tid >> 4;     // 0..7
    const int wt  = tid & 15;     // 0..15
    const int w0  = wt * 8;

    const float* xn = x + (size_t)n * CIN * HIN * WIN;
    float* yg = g_y + (size_t)(n * COUT + g * CPG) * OH * WPAD;

    ull ts = 0ull, tq = 0ull;     // packed (0.f, 0.f)

    for (int chunk = 0; chunk < 16; ++chunk) {
        const int r0 = chunk * TH;
        __syncthreads();

        // Load tile: 8 ic x 10 rows x 32 float4 = 2560 float4 (20 per thread)
        for (int idx = tid; idx < CIN * TROWS * 32; idx += 128) {
            int ic  = idx / (TROWS * 32);
            int rem = idx - ic * (TROWS * 32);
            int r   = rem >> 5;
            int c4  = rem & 31;
            int ih  = r0 + r;
            float4 v = make_float4(0.f, 0.f, 0.f, 0.f);
            if (ih < HIN)
                v = *(const float4*)(xn + ((size_t)ic * HIN + ih) * WIN + c4 * 4);
            s_in[ic][r][c4] = v;
        }
        if (tid < CIN * TROWS) {
            int ic = tid / TROWS, r = tid - ic * TROWS;
            s_in[ic][r][32] = make_float4(0.f, 0.f, 0.f, 0.f);
        }
        __syncthreads();

        const int orow = r0 + row;
        if (orow < OH) {
            ull acc[CPG][4] = {};

            #pragma unroll 2
            for (int ic = 0; ic < CIN; ++ic) {
                #pragma unroll
                for (int kh = 0; kh < 3; ++kh) {
                    const float4* rp = &s_in[ic][row + kh][0];
                    float4 A = rp[2 * wt];
                    float4 B = rp[2 * wt + 1];
                    float4 C = rp[2 * wt + 2];
                    ull pr[9];
                    pr[0] = pk2(A.x, A.y); pr[1] = pk2(A.y, A.z);
                    pr[2] = pk2(A.z, A.w); pr[3] = pk2(A.w, B.x);
                    pr[4] = pk2(B.x, B.y); pr[5] = pk2(B.y, B.z);
                    pr[6] = pk2(B.z, B.w); pr[7] = pk2(B.w, C.x);
                    pr[8] = pk2(C.x, C.y);
                    const ull* wv = &s_wp[ic][kh][0];
                    #pragma unroll
                    for (int oc = 0; oc < CPG; ++oc) {
                        ull wx = wv[oc * 3 + 0];
                        ull wy = wv[oc * 3 + 1];
                        ull wz = wv[oc * 3 + 2];
                        #pragma unroll
                        for (int pp = 0; pp < 4; ++pp) {
                            fma2(acc[oc][pp], pr[2 * pp + 0], wx);
                            fma2(acc[oc][pp], pr[2 * pp + 1], wy);
                            fma2(acc[oc][pp], pr[2 * pp + 2], wz);
                        }
                    }
                }
            }

            const bool full = (wt < 15);   // pair3 of wt==15 is cols 126,127 (invalid)
            #pragma unroll
            for (int oc = 0; oc < CPG; ++oc) {
                float b = s_bias[oc];
                ull b2 = pk2(b, b);
                ull v[4];
                #pragma unroll
                for (int pp = 0; pp < 4; ++pp) v[pp] = add2(acc[oc][pp], b2);

                float* dst = yg + ((size_t)oc * OH + orow) * WPAD + w0;
                *(ulonglong2*)dst       = make_ulonglong2(v[0], v[1]);
                *(ulonglong2*)(dst + 4) = make_ulonglong2(v[2], v[3]);

                #pragma unroll
                for (int pp = 0; pp < 3; ++pp) {
                    ts = add2(ts, v[pp]);
                    fma2(tq, v[pp], v[pp]);
                }
                if (full) { ts = add2(ts, v[3]); fma2(tq, v[3], v[3]); }
            }
        }
    }

    float slo, shi, qlo, qhi;
    unpk(ts, slo, shi); unpk(tq, qlo, qhi);
    float tsum = slo + shi, tsq = qlo + qhi;

    __syncthreads();
    s_red[tid]       = tsum;
    s_red[128 + tid] = tsq;
    __syncthreads();
    for (int s = 64; s > 0; s >>= 1) {
        if (tid < s) {
            s_red[tid]       += s_red[tid + s];
            s_red[128 + tid] += s_red[128 + tid + s];
        }
        __syncthreads();
    }
    if (tid == 0) {
        g_sum[n * G_ + g] = s_red[0];
        g_sqs[n * G_ + g] = s_red[128];
    }
}

// ---------------------------------------------------------------------------
// Kernel 2: finalize stats -> mean, rsig per (n, group)
// ---------------------------------------------------------------------------
__global__ void stats_finalize_kernel()
{
    int i = blockIdx.x * blockDim.x + threadIdx.x;
    if (i < N_ * G_) {
        const float inv_cnt = 1.f / (float)(CPG * OH * OW);
        float mean = g_sum[i] * inv_cnt;
        float var  = g_sqs[i] * inv_cnt - mean * mean;
        g_mean[i] = mean;
        g_rsig[i] = rsqrtf(var + 1e-5f);
    }
}

// ---------------------------------------------------------------------------
// Kernel 3: GN affine + per-channel scale folded into (a,b), 4x4 maxpool, clamp
// ---------------------------------------------------------------------------
__global__ __launch_bounds__(256) void pool_kernel(
    const float* __restrict__ gnw,
    const float* __restrict__ gnb,
    const float* __restrict__ scale,
    float* __restrict__ out)
{
    const int total = N_ * COUT * OPH * OPW;
    int idx = blockIdx.x * 256 + threadIdx.x;
    if (idx >= total) return;

    int j = idx % OPW;
    int t = idx / OPW;
    int i = t % OPH;  t /= OPH;
    int c = t % COUT;
    int n = t / COUT;

    int gi = n * G_ + (c >> 2);
    float mean = g_mean[gi];
    float rsig = g_rsig[gi];
    float sw   = scale[c];
    float gw   = gnw[c];
    float a = rsig * gw * sw;
    float b = (gnb[c] - mean * rsig * gw) * sw;

    const float* base = g_y + (((size_t)(n * COUT + c)) * OH + (size_t)i * 4) * WPAD + j * 4;
    float m = -3.4e38f;
    #pragma unroll
    for (int r = 0; r < 4; ++r) {
        float4 v = *(const float4*)(base + (size_t)r * WPAD);
        float m0 = fmaxf(fmaf(v.x, a, b), fmaf(v.y, a, b));
        float m1 = fmaxf(fmaf(v.z, a, b), fmaf(v.w, a, b));
        m = fmaxf(m, fmaxf(m0, m1));
    }
    out[idx] = fminf(fmaxf(m, 0.f), 1.f);
}

// ---------------------------------------------------------------------------
extern "C" void kernel_launch(void* const* d_in, const int* in_sizes, int n_in,
                              void* d_out, int out_size)
{
    const float* x     = (const float*)d_in[0];
    const float* cw    = (const float*)d_in[1];
    const float* cb    = (const float*)d_in[2];
    const float* gnw   = (const float*)d_in[3];
    const float* gnb   = (const float*)d_in[4];
    const float* scale = (const float*)d_in[5];
    float* out = (float*)d_out;

    dim3 grid1(G_, N_);
    conv_stats_kernel<<<grid1, 128>>>(x, cw, cb);

    stats_finalize_kernel<<<(N_ * G_ + 255) / 256, 256>>>();

    const int total = N_ * COUT * OPH * OPW;
    pool_kernel<<<(total + 255) / 256, 256>>>(gnw, gnb, scale, out);
}

// round 3
// speedup vs baseline: 1.3245x; 1.3245x over previous
#include <cuda_runtime.h>
#include <cstddef>

#define N_    128
#define CIN   8
#define HIN   128
#define WIN   128
#define COUT  64
#define OH    126
#define OW    126
#define G_    16
#define CPG   4
#define OPH   31
#define OPW   31
#define TH    8            // output rows per chunk
#define TROWS (TH + 2)

// Scratch: per-pool-window max/min of conv output (31.5 MB each)
__device__ float g_mx[(size_t)N_ * COUT * OPH * OPW];
__device__ float g_mn[(size_t)N_ * COUT * OPH * OPW];
__device__ float g_sum[N_ * G_];
__device__ float g_sqs[N_ * G_];
__device__ float g_mean[N_ * G_];
__device__ float g_rsig[N_ * G_];

// ---------------------------------------------------------------------------
// Kernel 1: conv(3x3, 8ic -> 4 oc of this group) + bias, fused 4x4 max/min
// pooling, deterministic block reduction of sum/sumsq for GroupNorm.
// One block per (group, n). 256 threads: row = tid>>5 (0..7), wg = tid&31.
// Each thread: 4 oc x 4 adjacent w (one pool-window column).
// ---------------------------------------------------------------------------
__global__ __launch_bounds__(256) void conv_stats_kernel(
    const float* __restrict__ x,
    const float* __restrict__ cw,
    const float* __restrict__ cb)
{
    __shared__ float4 s_in[CIN][TROWS][33];   // 42240 B
    __shared__ float4 s_w[CIN][3][CPG];       // broadcast (w0,w1,w2,0)
    __shared__ float  s_bias[CPG];
    __shared__ float  s_red[512];
    __shared__ float2 s_pool[TH][32][CPG];    // per-thread (max,min), 8192 B

    const int g   = blockIdx.x;
    const int n   = blockIdx.y;
    const int tid = threadIdx.x;

    if (tid < 96) {
        int oc = tid & 3;
        int t  = tid >> 2;
        int ic = t / 3, kh = t - 3 * ic;
        const float* wp = cw + ((((size_t)g * CPG + oc) * CIN + ic) * 3 + kh) * 3;
        s_w[ic][kh][oc] = make_float4(wp[0], wp[1], wp[2], 0.f);
    }
    if (tid < CPG) s_bias[tid] = cb[g * CPG + tid];

    const int row = tid >> 5;
    const int wg  = tid & 31;
    const int w0  = wg * 4;

    // decode for the pool-reduce phase (256 threads = 2 prow x 32 wg x 4 oc)
    const int prow = tid >> 7;
    const int pwg  = (tid >> 2) & 31;
    const int poc  = tid & 3;

    const float* xn = x + (size_t)n * CIN * HIN * WIN;

    float tsum = 0.f, tsq = 0.f;

    for (int chunk = 0; chunk < 16; ++chunk) {
        const int r0 = chunk * TH;
        __syncthreads();   // s_in free (prev compute done), s_pool free (prev reduce done)

        // Load input tile: 8 ic x 10 rows x 32 float4
        for (int idx = tid; idx < CIN * TROWS * 32; idx += 256) {
            int ic  = idx / (TROWS * 32);
            int rem = idx - ic * (TROWS * 32);
            int r   = rem >> 5;
            int c4  = rem & 31;
            int ih  = r0 + r;
            float4 v = make_float4(0.f, 0.f, 0.f, 0.f);
            if (ih < HIN)
                v = *(const float4*)(xn + ((size_t)ic * HIN + ih) * WIN + c4 * 4);
            s_in[ic][r][c4] = v;
        }
        if (tid < CIN * TROWS) {
            int ic = tid / TROWS, r = tid - ic * TROWS;
            s_in[ic][r][32] = make_float4(0.f, 0.f, 0.f, 0.f);
        }
        __syncthreads();

        const int orow = r0 + row;
        if (orow < OH) {
            float acc[CPG][4];
            #pragma unroll
            for (int oc = 0; oc < CPG; ++oc) {
                acc[oc][0] = 0.f; acc[oc][1] = 0.f;
                acc[oc][2] = 0.f; acc[oc][3] = 0.f;
            }

            #pragma unroll 2
            for (int ic = 0; ic < CIN; ++ic) {
                #pragma unroll
                for (int kh = 0; kh < 3; ++kh) {
                    float4 A = s_in[ic][row + kh][wg];
                    float4 B = s_in[ic][row + kh][wg + 1];
                    float i0 = A.x, i1 = A.y, i2 = A.z, i3 = A.w, i4 = B.x, i5 = B.y;
                    #pragma unroll
                    for (int oc = 0; oc < CPG; ++oc) {
                        float4 wv = s_w[ic][kh][oc];
                        acc[oc][0] = fmaf(i2, wv.z, fmaf(i1, wv.y, fmaf(i0, wv.x, acc[oc][0])));
                        acc[oc][1] = fmaf(i3, wv.z, fmaf(i2, wv.y, fmaf(i1, wv.x, acc[oc][1])));
                        acc[oc][2] = fmaf(i4, wv.z, fmaf(i3, wv.y, fmaf(i2, wv.x, acc[oc][2])));
                        acc[oc][3] = fmaf(i5, wv.z, fmaf(i4, wv.y, fmaf(i3, wv.x, acc[oc][3])));
                    }
                }
            }

            const bool full = (wg < 31);   // wg==31: only cols 124,125 valid; not pooled
            #pragma unroll
            for (int oc = 0; oc < CPG; ++oc) {
                float b  = s_bias[oc];
                float v0 = acc[oc][0] + b;
                float v1 = acc[oc][1] + b;
                float v2 = acc[oc][2] + b;
                float v3 = acc[oc][3] + b;

                tsum += v0 + v1;
                tsq  = fmaf(v0, v0, tsq); tsq = fmaf(v1, v1, tsq);
                if (full) {
                    tsum += v2 + v3;
                    tsq  = fmaf(v2, v2, tsq); tsq = fmaf(v3, v3, tsq);
                    float mx = fmaxf(fmaxf(v0, v1), fmaxf(v2, v3));
                    float mn = fminf(fminf(v0, v1), fminf(v2, v3));
                    s_pool[row][wg][oc] = make_float2(mx, mn);
                }
            }
        }
        __syncthreads();

        // Pool reduce: 2 pool rows x 31 cols x 4 oc -> gmem (max,min)
        const int prow_g = chunk * 2 + prow;
        if (pwg < 31 && prow_g < OPH) {
            float2 a0 = s_pool[prow * 4 + 0][pwg][poc];
            float2 a1 = s_pool[prow * 4 + 1][pwg][poc];
            float2 a2 = s_pool[prow * 4 + 2][pwg][poc];
            float2 a3 = s_pool[prow * 4 + 3][pwg][poc];
            float mx = fmaxf(fmaxf(a0.x, a1.x), fmaxf(a2.x, a3.x));
            float mn = fminf(fminf(a0.y, a1.y), fminf(a2.y, a3.y));
            size_t o = ((size_t)(n * COUT + g * CPG + poc) * OPH + prow_g) * OPW + pwg;
            g_mx[o] = mx;
            g_mn[o] = mn;
        }
    }

    // Deterministic block reduction (256 -> 1)
    __syncthreads();
    s_red[tid]       = tsum;
    s_red[256 + tid] = tsq;
    __syncthreads();
    for (int s = 128; s > 0; s >>= 1) {
        if (tid < s) {
            s_red[tid]       += s_red[tid + s];
            s_red[256 + tid] += s_red[256 + tid + s];
        }
        __syncthreads();
    }
    if (tid == 0) {
        g_sum[n * G_ + g] = s_red[0];
        g_sqs[n * G_ + g] = s_red[256];
    }
}

// ---------------------------------------------------------------------------
// Kernel 2: finalize stats -> mean, rsig per (n, group)
// ---------------------------------------------------------------------------
__global__ void stats_finalize_kernel()
{
    int i = blockIdx.x * blockDim.x + threadIdx.x;
    if (i < N_ * G_) {
        const float inv_cnt = 1.f / (float)(CPG * OH * OW);
        float mean = g_sum[i] * inv_cnt;
        float var  = g_sqs[i] * inv_cnt - mean * mean;
        g_mean[i] = mean;
        g_rsig[i] = rsqrtf(var + 1e-5f);
    }
}

// ---------------------------------------------------------------------------
// Kernel 3: affine (GN + scale folded) applied to pooled (max,min), clamp.
// out = clamp(a>0 ? a*max+b : a*min+b) — exact: max-pool commutes with
// monotone affine; for a<0 the window max of a*y+b is at the window min.
// ---------------------------------------------------------------------------
__global__ __launch_bounds__(256) void finalize_pool_kernel(
    const float* __restrict__ gnw,
    const float* __restrict__ gnb,
    const float* __restrict__ scale,
    float* __restrict__ out)
{
    const int total = N_ * COUT * OPH * OPW;
    int idx = blockIdx.x * 256 + threadIdx.x;
    if (idx >= total) return;

    int t = idx / (OPH * OPW);
    int c = t % COUT;
    int n = t / COUT;

    int gi = n * G_ + (c >> 2);
    float mean = g_mean[gi];
    float rsig = g_rsig[gi];
    float sw   = scale[c];
    float gw   = gnw[c];
    float a = rsig * gw * sw;
    float b = (gnb[c] - mean * rsig * gw) * sw;

    float v = (a > 0.f) ? fmaf(g_mx[idx], a, b) : fmaf(g_mn[idx], a, b);
    out[idx] = fminf(fmaxf(v, 0.f), 1.f);
}

// ---------------------------------------------------------------------------
extern "C" void kernel_launch(void* const* d_in, const int* in_sizes, int n_in,
                              void* d_out, int out_size)
{
    const float* x     = (const float*)d_in[0];
    const float* cw    = (const float*)d_in[1];
    const float* cb    = (const float*)d_in[2];
    const float* gnw   = (const float*)d_in[3];
    const float* gnb   = (const float*)d_in[4];
    const float* scale = (const float*)d_in[5];
    float* out = (float*)d_out;

    dim3 grid1(G_, N_);
    conv_stats_kernel<<<grid1, 256>>>(x, cw, cb);

    stats_finalize_kernel<<<(N_ * G_ + 255) / 256, 256>>>();

    const int total = N_ * COUT * OPH * OPW;
    finalize_pool_kernel<<<(total + 255) / 256, 256>>>(gnw, gnb, scale, out);
}

// round 5
// speedup vs baseline: 2.2505x; 1.6991x over previous
#include <cuda_runtime.h>
#include <cstdint>
#include <cstddef>

#define N_    128
#define CIN   8
#define HIN   128
#define WIN   128
#define COUT  64
#define OH    126
#define OW    126
#define G_    16
#define OPH   31
#define OPW   31

#define HB_   16     // 8 output rows per block
#define WB_   4      // 32 output cols per block
#define NTILES (N_ * HB_ * WB_)

// ---- smem layout (bytes) ----
#define OFF_B    0                    // 72*72*4      = 20736
#define OFF_A    20736                // 72*264*4     = 76032
#define OFF_OUT  20736                // union with A: 256*67*4 = 68608
#define OFF_X    96768                // 8*10*36*4    = 11520
#define OFF_CB   108288               // 64*4
#define OFF_RED  108544               // 512*4
#define SMEM_TOTAL 110592

#define SA 264                        // A k-major stride (px dim), 8 mod 32 -> frag LDS conflict-free
#define SB 72                         // B k-major stride (oc dim), 8 mod 32
#define SO 67                         // s_out px stride (odd -> stats scan conflict-free)

// ---- device scratch ----
__device__ uint32_t g_Bsw[72 * 72];                      // tf32 weights, k-major [k][oc]
__device__ float g_mx[(size_t)N_ * COUT * OPH * OPW];
__device__ float g_mn[(size_t)N_ * COUT * OPH * OPW];
__device__ float g_ps[NTILES * G_];
__device__ float g_pq[NTILES * G_];
__device__ float g_mean[N_ * G_];
__device__ float g_rsig[N_ * G_];

__device__ __forceinline__ uint32_t f2tf32(float v) {
    uint32_t r; asm("cvt.rna.tf32.f32 %0, %1;" : "=r"(r) : "f"(v)); return r;
}

__device__ __forceinline__ void mma8(float* c, const uint32_t* a, uint32_t b0, uint32_t b1) {
    asm volatile(
        "mma.sync.aligned.m16n8k8.row.col.f32.tf32.tf32.f32 "
        "{%0,%1,%2,%3}, {%4,%5,%6,%7}, {%8,%9}, {%0,%1,%2,%3};"
        : "+f"(c[0]), "+f"(c[1]), "+f"(c[2]), "+f"(c[3])
        : "r"(a[0]), "r"(a[1]), "r"(a[2]), "r"(a[3]), "r"(b0), "r"(b1));
}

// ---------------------------------------------------------------------------
// Kernel 0: weights -> tf32, k-major [k=ic*9+kh*3+kw][oc], pad oc 64..71 = 0
// ---------------------------------------------------------------------------
__global__ void bprep_kernel(const float* __restrict__ cw)
{
    int e = blockIdx.x * blockDim.x + threadIdx.x;
    if (e >= 72 * 72) return;
    int k = e / 72, c = e - (e / 72) * 72;
    float v = 0.f;
    if (c < 64) {
        int ic = k / 9, r = k % 9;
        v = cw[((c * 8 + ic) * 3 + r / 3) * 3 + (r % 3)];
    }
    g_Bsw[k * 72 + c] = f2tf32(v);
}

// ---------------------------------------------------------------------------
// Kernel 1: implicit-GEMM conv via mma.sync tf32 + bias + fused 4x4 max/min
// pool + per-group partial sums. 256 threads, grid (wb, hb, n).
// Tile: 8 output rows x 32 cols = 256 px (M), 64 oc (N), K = 72.
// Warp w owns output row h0+w (px 32w..32w+31) -> 2 m16 tiles x 8 n8 tiles.
// ---------------------------------------------------------------------------
__global__ __launch_bounds__(256, 2)
void conv_mma_kernel(const float* __restrict__ x, const float* __restrict__ cb)
{
    extern __shared__ char smem[];
    uint32_t* sB  = (uint32_t*)(smem + OFF_B);
    uint32_t* sA  = (uint32_t*)(smem + OFF_A);
    float*    sO  = (float*)(smem + OFF_OUT);
    float*    sX  = (float*)(smem + OFF_X);
    float*    sCb = (float*)(smem + OFF_CB);
    float*    sRd = (float*)(smem + OFF_RED);

    const int tid  = threadIdx.x;
    const int wid  = tid >> 5;
    const int lane = tid & 31;
    const int wb = blockIdx.x, hb = blockIdx.y, n = blockIdx.z;
    const int h0 = hb * 8, w0 = wb * 32;

    // copy pre-converted weights (1296 float4)
    {
        const float4* src = (const float4*)g_Bsw;
        float4* dst = (float4*)sB;
        #pragma unroll 2
        for (int i = tid; i < 1296; i += 256) dst[i] = src[i];
    }
    if (tid < 64) sCb[tid] = cb[tid];

    // stage x: 8 ic x 10 rows x 36 cols (zero-padded at edges)
    for (int idx = tid; idx < 720; idx += 256) {
        int ic  = idx / 90, rem = idx - ic * 90;
        int hr  = rem / 9,  c4  = rem - hr * 9;
        int h = h0 + hr, gw = w0 + c4 * 4;
        float4 v = make_float4(0.f, 0.f, 0.f, 0.f);
        if (h < HIN) {
            const float* rp = x + (((size_t)n * CIN + ic) * HIN + h) * WIN;
            if (gw + 3 < WIN) v = *(const float4*)(rp + gw);
            else {
                if (gw + 0 < WIN) v.x = rp[gw + 0];
                if (gw + 1 < WIN) v.y = rp[gw + 1];
                if (gw + 2 < WIN) v.z = rp[gw + 2];
            }
        }
        *(float4*)(sX + (ic * 10 + hr) * 36 + c4 * 4) = v;
    }
    __syncthreads();

    // im2col: thread = px (hh = tid>>5, ww = tid&31); A[k][px], k-major.
    // STS conflict-free (32 consecutive px per warp).
    {
        const int hh = tid >> 5, ww = tid & 31;
        #pragma unroll 2
        for (int ic = 0; ic < CIN; ++ic) {
            const float* xr = sX + ic * 360;
            #pragma unroll
            for (int r = 0; r < 9; ++r) {
                const int kh = r / 3, kw = r % 3;
                float v = xr[(hh + kh) * 36 + ww + kw];
                sA[(ic * 9 + r) * SA + tid] = f2tf32(v);
            }
        }
    }
    __syncthreads();

    // ---- MMA mainloop: 9 k-steps of 8 ----
    float acc[2][8][4];
    #pragma unroll
    for (int t = 0; t < 2; ++t)
        #pragma unroll
        for (int j = 0; j < 8; ++j)
            #pragma unroll
            for (int u = 0; u < 4; ++u) acc[t][j][u] = 0.f;

    const int q  = lane >> 2;   // 0..7
    const int r4 = lane & 3;    // 0..3

    #pragma unroll 3
    for (int kk = 0; kk < 9; ++kk) {
        const int k0 = kk * 8;
        uint32_t a[2][4];
        #pragma unroll
        for (int t = 0; t < 2; ++t) {
            const int pxb = (wid << 5) + (t << 4) + q;
            a[t][0] = sA[(k0 + r4) * SA + pxb];
            a[t][1] = sA[(k0 + r4) * SA + pxb + 8];
            a[t][2] = sA[(k0 + r4 + 4) * SA + pxb];
            a[t][3] = sA[(k0 + r4 + 4) * SA + pxb + 8];
        }
        #pragma unroll
        for (int j = 0; j < 8; ++j) {
            uint32_t b0 = sB[(k0 + r4) * SB + (j << 3) + q];
            uint32_t b1 = sB[(k0 + r4 + 4) * SB + (j << 3) + q];
            mma8(acc[0][j], a[0], b0, b1);
            mma8(acc[1][j], a[1], b0, b1);
        }
    }
    __syncthreads();   // A dead; region becomes s_out

    // ---- epilogue: +bias, validity-zeroing, -> s_out[px][oc] ----
    const bool hok = (h0 + wid) < OH;
    #pragma unroll
    for (int t = 0; t < 2; ++t) {
        const int ww0 = (t << 4) + q;
        const int px0 = (wid << 5) + ww0;
        const bool v0 = hok && (w0 + ww0 < OW);
        const bool v1 = hok && (w0 + ww0 + 8 < OW);
        #pragma unroll
        for (int j = 0; j < 8; ++j) {
            const int oc = (j << 3) + (r4 << 1);
            float b0 = sCb[oc], b1 = sCb[oc + 1];
            sO[px0 * SO + oc]           = v0 ? acc[t][j][0] + b0 : 0.f;
            sO[px0 * SO + oc + 1]       = v0 ? acc[t][j][1] + b1 : 0.f;
            sO[(px0 + 8) * SO + oc]     = v1 ? acc[t][j][2] + b0 : 0.f;
            sO[(px0 + 8) * SO + oc + 1] = v1 ? acc[t][j][3] + b1 : 0.f;
        }
    }
    __syncthreads();

    // ---- stats: column scan, 4 partials per oc, fixed order ----
    {
        const int oc = tid & 63, part = tid >> 6;
        const float* p = sO + part * 64 * SO + oc;
        float s = 0.f, qq = 0.f;
        #pragma unroll 8
        for (int i = 0; i < 64; ++i) {
            float v = p[i * SO];
            s += v; qq = fmaf(v, v, qq);
        }
        sRd[tid] = s; sRd[256 + tid] = qq;
    }
    __syncthreads();

    const int tile = (n * HB_ + hb) * WB_ + wb;
    if (tid < 16) {
        float S = 0.f, Q = 0.f;
        #pragma unroll
        for (int part = 0; part < 4; ++part)
            #pragma unroll
            for (int c2 = 0; c2 < 4; ++c2) {
                S += sRd[part * 64 + tid * 4 + c2];
                Q += sRd[256 + part * 64 + tid * 4 + c2];
            }
        g_ps[tile * G_ + tid] = S;
        g_pq[tile * G_ + tid] = Q;
    }

    // ---- pool: 2 pool rows x 8 cols x 64 oc = 1024 tasks, 4/thread ----
    #pragma unroll
    for (int i = 0; i < 4; ++i) {
        const int task = tid + (i << 8);
        const int oc = task & 63, j = (task >> 6) & 7, prl = task >> 9;
        const int pw = wb * 8 + j, pr = hb * 2 + prl;
        if (pw < OPW && pr < OPH) {
            float mx = -3.4e38f, mn = 3.4e38f;
            #pragma unroll
            for (int a2 = 0; a2 < 4; ++a2)
                #pragma unroll
                for (int b2 = 0; b2 < 4; ++b2) {
                    float v = sO[((prl * 4 + a2) * 32 + j * 4 + b2) * SO + oc];
                    mx = fmaxf(mx, v); mn = fminf(mn, v);
                }
            size_t o = ((size_t)(n * COUT + oc) * OPH + pr) * OPW + pw;
            g_mx[o] = mx; g_mn[o] = mn;
        }
    }
}

// ---------------------------------------------------------------------------
// Kernel 2: reduce per-tile partials -> mean, rsig. Fixed order.
// ---------------------------------------------------------------------------
__global__ void stats_reduce_kernel()
{
    int i = blockIdx.x * blockDim.x + threadIdx.x;
    if (i >= N_ * G_) return;
    int n = i / G_, g = i - n * G_;
    float S = 0.f, Q = 0.f;
    for (int hb = 0; hb < HB_; ++hb)
        for (int wbv = 0; wbv < WB_; ++wbv) {
            int tl = (n * HB_ + hb) * WB_ + wbv;
            S += g_ps[tl * G_ + g];
            Q += g_pq[tl * G_ + g];
        }
    const float inv_cnt = 1.f / (float)(4 * OH * OW);
    float mean = S * inv_cnt;
    float var  = Q * inv_cnt - mean * mean;
    g_mean[i] = mean;
    g_rsig[i] = rsqrtf(var + 1e-5f);
}

// ---------------------------------------------------------------------------
// Kernel 3: affine (GN + scale folded) on pooled (max,min), clamp.
// ---------------------------------------------------------------------------
__global__ __launch_bounds__(256) void finalize_pool_kernel(
    const float* __restrict__ gnw,
    const float* __restrict__ gnb,
    const float* __restrict__ scale,
    float* __restrict__ out)
{
    const int total = N_ * COUT * OPH * OPW;
    int idx = blockIdx.x * 256 + threadIdx.x;
    if (idx >= total) return;

    int t = idx / (OPH * OPW);
    int c = t % COUT;
    int n = t / COUT;

    int gi = n * G_ + (c >> 2);
    float mean = g_mean[gi];
    float rsig = g_rsig[gi];
    float a = rsig * gnw[c] * scale[c];
    float b = (gnb[c] - mean * rsig * gnw[c]) * scale[c];

    float v = (a > 0.f) ? fmaf(g_mx[idx], a, b) : fmaf(g_mn[idx], a, b);
    out[idx] = fminf(fmaxf(v, 0.f), 1.f);
}

// ---------------------------------------------------------------------------
extern "C" void kernel_launch(void* const* d_in, const int* in_sizes, int n_in,
                              void* d_out, int out_size)
{
    const float* x     = (const float*)d_in[0];
    const float* cw    = (const float*)d_in[1];
    const float* cb    = (const float*)d_in[2];
    const float* gnw   = (const float*)d_in[3];
    const float* gnb   = (const float*)d_in[4];
    const float* scale = (const float*)d_in[5];
    float* out = (float*)d_out;

    static bool attr_set = false;
    if (!attr_set) {
        cudaFuncSetAttribute(conv_mma_kernel,
                             cudaFuncAttributeMaxDynamicSharedMemorySize, SMEM_TOTAL);
        attr_set = true;
    }

    bprep_kernel<<<21, 256>>>(cw);

    dim3 grid(WB_, HB_, N_);
    conv_mma_kernel<<<grid, 256, SMEM_TOTAL>>>(x, cb);

    stats_reduce_kernel<<<(N_ * G_ + 255) / 256, 256>>>();

    const int total = N_ * COUT * OPH * OPW;
    finalize_pool_kernel<<<(total + 255) / 256, 256>>>(gnw, gnb, scale, out);
}

// round 6
// speedup vs baseline: 2.6698x; 1.1863x over previous
#include <cuda_runtime.h>
#include <cstdint>
#include <cstddef>

#define N_    128
#define CIN   8
#define HIN   128
#define WIN   128
#define COUT  64
#define OH    126
#define OW    126
#define G_    16
#define OPH   31
#define OPW   31

#define HB_   16     // 8 output rows per block
#define WB_   4      // 32 output cols per block
#define NTILES (N_ * HB_ * WB_)

// ---- smem layout (bytes) ----
// phase 1 (stage + mainloop):  sB [0,20736), sX [20736,32256)
// phase 2 (epilogue/stats/pool): sO [0,73728)  (aliases sB+sX)
#define OFF_B    0
#define OFF_X    20736
#define OFF_OUT  0
#define OFF_CB   73728
#define OFF_RED  73984
#define SMEM_TOTAL 76032

#define SB 72    // B k-major stride (oc dim)
#define SO 72    // s_out px stride: paired STS.64 -> conflict-free (4q+r4 inj. mod 16)

// ---- device scratch ----
__device__ uint32_t g_Bsw[72 * 72];                      // tf32 weights, k-major [k][oc]
__device__ float g_mx[(size_t)N_ * COUT * OPH * OPW];
__device__ float g_mn[(size_t)N_ * COUT * OPH * OPW];
__device__ float g_ps[NTILES * G_];
__device__ float g_pq[NTILES * G_];
__device__ float g_mean[N_ * G_];
__device__ float g_rsig[N_ * G_];

__device__ __forceinline__ uint32_t f2tf32(float v) {
    uint32_t r; asm("cvt.rna.tf32.f32 %0, %1;" : "=r"(r) : "f"(v)); return r;
}

__device__ __forceinline__ void mma8(float* c, const uint32_t* a, uint32_t b0, uint32_t b1) {
    asm volatile(
        "mma.sync.aligned.m16n8k8.row.col.f32.tf32.tf32.f32 "
        "{%0,%1,%2,%3}, {%4,%5,%6,%7}, {%8,%9}, {%0,%1,%2,%3};"
        : "+f"(c[0]), "+f"(c[1]), "+f"(c[2]), "+f"(c[3])
        : "r"(a[0]), "r"(a[1]), "r"(a[2]), "r"(a[3]), "r"(b0), "r"(b1));
}

// k (< 76) -> smem offset ic*360 + kh*36 + kw  (sX layout [ic][10][36])
__device__ __forceinline__ int koff(int k) {
    int ic = (k * 57) >> 9;        // k/9 for k < 81
    int r  = k - 9 * ic;
    int kh = (r * 11) >> 5;        // r/3 for r < 9
    int kw = r - 3 * kh;
    return ic * 360 + kh * 36 + kw;
}

// ---------------------------------------------------------------------------
// Kernel 0: weights -> tf32, k-major [k=ic*9+kh*3+kw][oc], pad oc 64..71 = 0
// ---------------------------------------------------------------------------
__global__ void bprep_kernel(const float* __restrict__ cw)
{
    int e = blockIdx.x * blockDim.x + threadIdx.x;
    if (e >= 72 * 72) return;
    int k = e / 72, c = e - (e / 72) * 72;
    float v = 0.f;
    if (c < 64) {
        int ic = k / 9, r = k % 9;
        v = cw[((c * 8 + ic) * 3 + r / 3) * 3 + (r % 3)];
    }
    g_Bsw[k * 72 + c] = f2tf32(v);
}

// ---------------------------------------------------------------------------
// Kernel 1: implicit-GEMM conv via mma.sync tf32 + bias + fused 4x4 max/min
// pool + per-group partial sums. 256 threads, grid (wb, hb, n).
// Tile: 8 output rows x 32 cols = 256 px (M), 64 oc (N), K = 72.
// A fragments gathered directly from staged input (no im2col stage).
// ---------------------------------------------------------------------------
__global__ __launch_bounds__(256, 2)
void conv_mma_kernel(const float* __restrict__ x, const float* __restrict__ cb)
{
    extern __shared__ char smem[];
    uint32_t* sB  = (uint32_t*)(smem + OFF_B);
    float*    sX  = (float*)(smem + OFF_X);    // [ic][10][36]
    float*    sO  = (float*)(smem + OFF_OUT);  // [256][SO], aliases sB+sX
    float*    sCb = (float*)(smem + OFF_CB);
    float*    sRd = (float*)(smem + OFF_RED);

    const int tid  = threadIdx.x;
    const int wid  = tid >> 5;
    const int lane = tid & 31;
    const int wb = blockIdx.x, hb = blockIdx.y, n = blockIdx.z;
    const int h0 = hb * 8, w0 = wb * 32;

    const int q  = lane >> 2;   // 0..7
    const int r4 = lane & 3;    // 0..3

    // copy pre-converted weights (1296 float4)
    {
        const float4* src = (const float4*)g_Bsw;
        float4* dst = (float4*)sB;
        #pragma unroll 2
        for (int i = tid; i < 1296; i += 256) dst[i] = src[i];
    }
    if (tid < 64) sCb[tid] = cb[tid];

    // stage x: 8 ic x 10 rows x 36 cols (zero-padded at edges)
    for (int idx = tid; idx < 720; idx += 256) {
        int ic  = idx / 90, rem = idx - ic * 90;
        int hr  = rem / 9,  c4  = rem - hr * 9;
        int h = h0 + hr, gw = w0 + c4 * 4;
        float4 v = make_float4(0.f, 0.f, 0.f, 0.f);
        if (h < HIN) {
            const float* rp = x + (((size_t)n * CIN + ic) * HIN + h) * WIN;
            if (gw + 3 < WIN) v = *(const float4*)(rp + gw);
            else {
                if (gw + 0 < WIN) v.x = rp[gw + 0];
                if (gw + 1 < WIN) v.y = rp[gw + 1];
                if (gw + 2 < WIN) v.z = rp[gw + 2];
            }
        }
        *(float4*)(sX + (ic * 10 + hr) * 36 + c4 * 4) = v;
    }
    __syncthreads();

    // per-thread A gather offsets: k = 8*kk + r4 (+4)
    int off0[9], off1[9];
    #pragma unroll
    for (int kk = 0; kk < 9; ++kk) {
        off0[kk] = koff(8 * kk + r4);
        off1[kk] = koff(8 * kk + r4 + 4);
    }
    const int ab = wid * 36 + q;   // + 16*t (+8 for high px half)

    // ---- MMA mainloop: 9 k-steps of 8 ----
    float acc[2][8][4];
    #pragma unroll
    for (int t = 0; t < 2; ++t)
        #pragma unroll
        for (int j = 0; j < 8; ++j)
            #pragma unroll
            for (int u = 0; u < 4; ++u) acc[t][j][u] = 0.f;

    #pragma unroll
    for (int kk = 0; kk < 9; ++kk) {
        const int k0 = kk * 8;
        uint32_t a[2][4];
        #pragma unroll
        for (int t = 0; t < 2; ++t) {
            const float* p0 = sX + off0[kk] + ab + t * 16;
            const float* p1 = sX + off1[kk] + ab + t * 16;
            a[t][0] = f2tf32(p0[0]);
            a[t][1] = f2tf32(p0[8]);
            a[t][2] = f2tf32(p1[0]);
            a[t][3] = f2tf32(p1[8]);
        }
        #pragma unroll
        for (int j = 0; j < 8; ++j) {
            uint32_t b0 = sB[(k0 + r4) * SB + (j << 3) + q];
            uint32_t b1 = sB[(k0 + r4 + 4) * SB + (j << 3) + q];
            mma8(acc[0][j], a[0], b0, b1);
            mma8(acc[1][j], a[1], b0, b1);
        }
    }
    __syncthreads();   // sB/sX dead; region becomes s_out

    // ---- epilogue: +bias, validity-zeroing, paired STS.64 -> s_out[px][oc] ----
    const bool hok = (h0 + wid) < OH;
    #pragma unroll
    for (int t = 0; t < 2; ++t) {
        const int ww0 = (t << 4) + q;
        const int px0 = (wid << 5) + ww0;
        const bool v0 = hok && (w0 + ww0 < OW);
        const bool v1 = hok && (w0 + ww0 + 8 < OW);
        #pragma unroll
        for (int j = 0; j < 8; ++j) {
            const int oc = (j << 3) + (r4 << 1);
            float2 bc = *(float2*)(sCb + oc);
            float2 e0, e1;
            e0.x = v0 ? acc[t][j][0] + bc.x : 0.f;
            e0.y = v0 ? acc[t][j][1] + bc.y : 0.f;
            e1.x = v1 ? acc[t][j][2] + bc.x : 0.f;
            e1.y = v1 ? acc[t][j][3] + bc.y : 0.f;
            *(float2*)(sO + px0 * SO + oc)       = e0;
            *(float2*)(sO + (px0 + 8) * SO + oc) = e1;
        }
    }
    __syncthreads();

    // ---- stats: column scan, 4 partials per oc, fixed order ----
    {
        const int oc = tid & 63, part = tid >> 6;
        const float* p = sO + part * 64 * SO + oc;
        float s = 0.f, qq = 0.f;
        #pragma unroll 8
        for (int i = 0; i < 64; ++i) {
            float v = p[i * SO];
            s += v; qq = fmaf(v, v, qq);
        }
        sRd[tid] = s; sRd[256 + tid] = qq;
    }
    __syncthreads();

    const int tile = (n * HB_ + hb) * WB_ + wb;
    if (tid < 16) {
        float S = 0.f, Q = 0.f;
        #pragma unroll
        for (int part = 0; part < 4; ++part)
            #pragma unroll
            for (int c2 = 0; c2 < 4; ++c2) {
                S += sRd[part * 64 + tid * 4 + c2];
                Q += sRd[256 + part * 64 + tid * 4 + c2];
            }
        g_ps[tile * G_ + tid] = S;
        g_pq[tile * G_ + tid] = Q;
    }

    // ---- pool: 2 pool rows x 8 cols x 64 oc = 1024 tasks, 4/thread ----
    #pragma unroll
    for (int i = 0; i < 4; ++i) {
        const int task = tid + (i << 8);
        const int oc = task & 63, j = (task >> 6) & 7, prl = task >> 9;
        const int pw = wb * 8 + j, pr = hb * 2 + prl;
        if (pw < OPW && pr < OPH) {
            float mx = -3.4e38f, mn = 3.4e38f;
            #pragma unroll
            for (int a2 = 0; a2 < 4; ++a2)
                #pragma unroll
                for (int b2 = 0; b2 < 4; ++b2) {
                    float v = sO[((prl * 4 + a2) * 32 + j * 4 + b2) * SO + oc];
                    mx = fmaxf(mx, v); mn = fminf(mn, v);
                }
            size_t o = ((size_t)(n * COUT + oc) * OPH + pr) * OPW + pw;
            g_mx[o] = mx; g_mn[o] = mn;
        }
    }
}

// ---------------------------------------------------------------------------
// Kernel 2: reduce per-tile partials -> mean, rsig. Fixed order.
// ---------------------------------------------------------------------------
__global__ void stats_reduce_kernel()
{
    int i = blockIdx.x * blockDim.x + threadIdx.x;
    if (i >= N_ * G_) return;
    int n = i / G_, g = i - n * G_;
    float S = 0.f, Q = 0.f;
    for (int hb = 0; hb < HB_; ++hb)
        for (int wbv = 0; wbv < WB_; ++wbv) {
            int tl = (n * HB_ + hb) * WB_ + wbv;
            S += g_ps[tl * G_ + g];
            Q += g_pq[tl * G_ + g];
        }
    const float inv_cnt = 1.f / (float)(4 * OH * OW);
    float mean = S * inv_cnt;
    float var  = Q * inv_cnt - mean * mean;
    g_mean[i] = mean;
    g_rsig[i] = rsqrtf(var + 1e-5f);
}

// ---------------------------------------------------------------------------
// Kernel 3: affine (GN + scale folded) on pooled (max,min), clamp.
// ---------------------------------------------------------------------------
__global__ __launch_bounds__(256) void finalize_pool_kernel(
    const float* __restrict__ gnw,
    const float* __restrict__ gnb,
    const float* __restrict__ scale,
    float* __restrict__ out)
{
    const int total = N_ * COUT * OPH * OPW;
    int idx = blockIdx.x * 256 + threadIdx.x;
    if (idx >= total) return;

    int t = idx / (OPH * OPW);
    int c = t % COUT;
    int n = t / COUT;

    int gi = n * G_ + (c >> 2);
    float mean = g_mean[gi];
    float rsig = g_rsig[gi];
    float a = rsig * gnw[c] * scale[c];
    float b = (gnb[c] - mean * rsig * gnw[c]) * scale[c];

    float v = (a > 0.f) ? fmaf(g_mx[idx], a, b) : fmaf(g_mn[idx], a, b);
    out[idx] = fminf(fmaxf(v, 0.f), 1.f);
}

// ---------------------------------------------------------------------------
extern "C" void kernel_launch(void* const* d_in, const int* in_sizes, int n_in,
                              void* d_out, int out_size)
{
    const float* x     = (const float*)d_in[0];
    const float* cw    = (const float*)d_in[1];
    const float* cb    = (const float*)d_in[2];
    const float* gnw   = (const float*)d_in[3];
    const float* gnb   = (const float*)d_in[4];
    const float* scale = (const float*)d_in[5];
    float* out = (float*)d_out;

    static bool attr_set = false;
    if (!attr_set) {
        cudaFuncSetAttribute(conv_mma_kernel,
                             cudaFuncAttributeMaxDynamicSharedMemorySize, SMEM_TOTAL);
        attr_set = true;
    }

    bprep_kernel<<<21, 256>>>(cw);

    dim3 grid(WB_, HB_, N_);
    conv_mma_kernel<<<grid, 256, SMEM_TOTAL>>>(x, cb);

    stats_reduce_kernel<<<(N_ * G_ + 255) / 256, 256>>>();

    const int total = N_ * COUT * OPH * OPW;
    finalize_pool_kernel<<<(total + 255) / 256, 256>>>(gnw, gnb, scale, out);
}

// round 7
// speedup vs baseline: 3.1560x; 1.1821x over previous
#include <cuda_runtime.h>
#include <cstdint>
#include <cstddef>

#define N_    128
#define CIN   8
#define HIN   128
#define WIN   128
#define COUT  64
#define OH    126
#define OW    126
#define G_    16
#define OPH   31
#define OPW   31

#define HB_   16
#define WB_   4
#define NTILES (N_ * HB_ * WB_)

// ---- smem layout (bytes) ----
// phase 1: sB2 [0,18432), sX [18432,29952)
// phase 2: sO [0,75776) (256 px x 74 floats), aliases phase-1 regions
#define OFF_B2   0
#define OFF_X    18432
#define OFF_OUT  0
#define OFF_CB   75776
#define OFF_RED  76032
#define OFF_SG   78080
#define SMEM_TOTAL 78336

#define SO 74    // s_out px stride: 37 f2 -> 4q+r4 bank-pairs, conflict-free

// ---- device scratch ----
__device__ uint2 g_B2[64 * 36];                 // tf32 weight pairs [oc][kk][r4] = (k, k+4)
__device__ float g_sgn[64];                     // +1 / -1 per oc
__device__ float g_ext[(size_t)N_ * COUT * OPH * OPW];
__device__ float g_ps[NTILES * G_];
__device__ float g_pq[NTILES * G_];
__device__ float g_mean[N_ * G_];
__device__ float g_rsig[N_ * G_];

__device__ __forceinline__ uint32_t f2tf32(float v) {
    uint32_t r; asm("cvt.rna.tf32.f32 %0, %1;" : "=r"(r) : "f"(v)); return r;
}

__device__ __forceinline__ void mma8(float* c, const uint32_t* a, uint32_t b0, uint32_t b1) {
    asm volatile(
        "mma.sync.aligned.m16n8k8.row.col.f32.tf32.tf32.f32 "
        "{%0,%1,%2,%3}, {%4,%5,%6,%7}, {%8,%9}, {%0,%1,%2,%3};"
        : "+f"(c[0]), "+f"(c[1]), "+f"(c[2]), "+f"(c[3])
        : "r"(a[0]), "r"(a[1]), "r"(a[2]), "r"(a[3]), "r"(b0), "r"(b1));
}

// k (< 76) -> sX offset ic*360 + kh*36 + kw   (sX layout [ic][10][36])
__device__ __forceinline__ int koff(int k) {
    int ic = (k * 57) >> 9;
    int r  = k - 9 * ic;
    int kh = (r * 11) >> 5;
    int kw = r - 3 * kh;
    return ic * 360 + kh * 36 + kw;
}

// ---------------------------------------------------------------------------
// Kernel 0: weights -> tf32 pairs (k, k+4) keyed [oc][kk][r4]; sign of a per oc
// ---------------------------------------------------------------------------
__global__ void bprep_kernel(const float* __restrict__ cw,
                             const float* __restrict__ gnw,
                             const float* __restrict__ scale)
{
    int e = blockIdx.x * blockDim.x + threadIdx.x;
    if (e < 64) g_sgn[e] = (gnw[e] * scale[e] > 0.f) ? 1.f : -1.f;
    if (e >= 64 * 36) return;
    int oc = e / 36, rem = e - (e / 36) * 36;
    int kk = rem >> 2, r4 = rem & 3;
    int k0 = 8 * kk + r4, k1 = k0 + 4;

    int ic0 = k0 / 9, r0 = k0 % 9;
    int ic1 = k1 / 9, r1 = k1 % 9;
    float w0 = cw[((oc * 8 + ic0) * 3 + r0 / 3) * 3 + (r0 % 3)];
    float w1 = cw[((oc * 8 + ic1) * 3 + r1 / 3) * 3 + (r1 % 3)];
    g_B2[e] = make_uint2(f2tf32(w0), f2tf32(w1));
}

// ---------------------------------------------------------------------------
// Kernel 1: implicit-GEMM conv (mma.sync tf32) + bias + fused pool extreme +
// per-group partials. 256 threads, grid (wb, hb, n).
// Lane->pixel permutation: tile row q -> px 4q+2t+h (h = m16 half).
// ---------------------------------------------------------------------------
__global__ __launch_bounds__(256, 2)
void conv_mma_kernel(const float* __restrict__ x, const float* __restrict__ cb)
{
    extern __shared__ char smem[];
    uint2*  sB2 = (uint2*)(smem + OFF_B2);
    float*  sX  = (float*)(smem + OFF_X);     // [ic][10][36]
    float*  sO  = (float*)(smem + OFF_OUT);   // [256][SO]
    float*  sCb = (float*)(smem + OFF_CB);
    float*  sRd = (float*)(smem + OFF_RED);
    float*  sSg = (float*)(smem + OFF_SG);

    const int tid  = threadIdx.x;
    const int wid  = tid >> 5;
    const int lane = tid & 31;
    const int wb = blockIdx.x, hb = blockIdx.y, n = blockIdx.z;
    const int h0 = hb * 8, w0 = wb * 32;

    const int q  = lane >> 2;
    const int r4 = lane & 3;

    // copy packed weights (1152 float4)
    {
        const float4* src = (const float4*)g_B2;
        float4* dst = (float4*)sB2;
        #pragma unroll 2
        for (int i = tid; i < 1152; i += 256) dst[i] = src[i];
    }
    if (tid < 64) { sCb[tid] = cb[tid]; sSg[tid] = g_sgn[tid]; }

    // stage x: 8 ic x 10 rows x 36 cols
    for (int idx = tid; idx < 720; idx += 256) {
        int ic  = idx / 90, rem = idx - ic * 90;
        int hr  = rem / 9,  c4  = rem - hr * 9;
        int h = h0 + hr, gw = w0 + c4 * 4;
        float4 v = make_float4(0.f, 0.f, 0.f, 0.f);
        if (h < HIN) {
            const float* rp = x + (((size_t)n * CIN + ic) * HIN + h) * WIN;
            if (gw + 3 < WIN) v = *(const float4*)(rp + gw);
            else {
                if (gw + 0 < WIN) v.x = rp[gw + 0];
                if (gw + 1 < WIN) v.y = rp[gw + 1];
                if (gw + 2 < WIN) v.z = rp[gw + 2];
            }
        }
        *(float4*)(sX + (ic * 10 + hr) * 36 + c4 * 4) = v;
    }
    __syncthreads();

    int off0[9], off1[9];
    #pragma unroll
    for (int kk = 0; kk < 9; ++kk) {
        off0[kk] = koff(8 * kk + r4);
        off1[kk] = koff(8 * kk + r4 + 4);
    }
    const int P = wid * 36 + 4 * q;

    float acc[2][8][4];
    #pragma unroll
    for (int t = 0; t < 2; ++t)
        #pragma unroll
        for (int j = 0; j < 8; ++j)
            #pragma unroll
            for (int u = 0; u < 4; ++u) acc[t][j][u] = 0.f;

    // ---- MMA mainloop ----
    #pragma unroll
    for (int kk = 0; kk < 9; ++kk) {
        const float* p0 = sX + off0[kk] + P;
        const float* p1 = sX + off1[kk] + P;
        uint32_t a[2][4];
        #pragma unroll
        for (int t = 0; t < 2; ++t) {
            a[t][0] = f2tf32(p0[2 * t]);      // row q     -> px 4q+2t
            a[t][1] = f2tf32(p0[2 * t + 1]);  // row q+8   -> px 4q+2t+1
            a[t][2] = f2tf32(p1[2 * t]);
            a[t][3] = f2tf32(p1[2 * t + 1]);
        }
        const uint2* bp = sB2 + q * 36 + kk * 4 + r4;
        #pragma unroll
        for (int j = 0; j < 8; ++j) {
            uint2 bv = bp[j * 288];           // (8j+q)*36
            mma8(acc[0][j], a[0], bv.x, bv.y);
            mma8(acc[1][j], a[1], bv.x, bv.y);
        }
    }
    __syncthreads();   // sB2/sX dead; region becomes s_out

    // ---- epilogue: +bias, zero invalid, paired STS.64 -> sO[px][oc] ----
    const bool hok = (h0 + wid) < OH;
    #pragma unroll
    for (int t = 0; t < 2; ++t) {
        const int ww0 = 4 * q + 2 * t;
        const int px  = (wid << 5) + ww0;
        const bool v0 = hok && (w0 + ww0 < OW);
        const bool v1 = hok && (w0 + ww0 + 1 < OW);
        #pragma unroll
        for (int j = 0; j < 8; ++j) {
            const int oc = (j << 3) + (r4 << 1);
            float2 bc = *(float2*)(sCb + oc);
            float2 e0, e1;
            e0.x = v0 ? acc[t][j][0] + bc.x : 0.f;   // row q     (px)
            e0.y = v0 ? acc[t][j][1] + bc.y : 0.f;
            e1.x = v1 ? acc[t][j][2] + bc.x : 0.f;   // row q+8   (px+1)
            e1.y = v1 ? acc[t][j][3] + bc.y : 0.f;
            *(float2*)(sO + px * SO + oc)       = e0;
            *(float2*)(sO + (px + 1) * SO + oc) = e1;
        }
    }
    __syncthreads();

    // ---- stats: column scan, 4 partials per oc, fixed order ----
    {
        const int oc = tid & 63, part = tid >> 6;
        const float* p = sO + part * 64 * SO + oc;
        float s = 0.f, qq = 0.f;
        #pragma unroll 8
        for (int i = 0; i < 64; ++i) {
            float v = p[i * SO];
            s += v; qq = fmaf(v, v, qq);
        }
        sRd[tid] = s; sRd[256 + tid] = qq;
    }
    __syncthreads();

    const int tile = (n * HB_ + hb) * WB_ + wb;
    if (tid < 16) {
        float S = 0.f, Q = 0.f;
        #pragma unroll
        for (int part = 0; part < 4; ++part)
            #pragma unroll
            for (int c2 = 0; c2 < 4; ++c2) {
                S += sRd[part * 64 + tid * 4 + c2];
                Q += sRd[256 + part * 64 + tid * 4 + c2];
            }
        g_ps[tile * G_ + tid] = S;
        g_pq[tile * G_ + tid] = Q;
    }

    // ---- pool: keep only the sign-relevant extreme ----
    #pragma unroll
    for (int i = 0; i < 4; ++i) {
        const int task = tid + (i << 8);
        const int oc = task & 63, j = (task >> 6) & 7, prl = task >> 9;
        const int pw = wb * 8 + j, pr = hb * 2 + prl;
        if (pw < OPW && pr < OPH) {
            float mx = -3.4e38f, mn = 3.4e38f;
            #pragma unroll
            for (int a2 = 0; a2 < 4; ++a2)
                #pragma unroll
                for (int b2 = 0; b2 < 4; ++b2) {
                    float v = sO[((prl * 4 + a2) * 32 + j * 4 + b2) * SO + oc];
                    mx = fmaxf(mx, v); mn = fminf(mn, v);
                }
            size_t o = ((size_t)(n * COUT + oc) * OPH + pr) * OPW + pw;
            g_ext[o] = (sSg[oc] > 0.f) ? mx : mn;
        }
    }
}

// ---------------------------------------------------------------------------
// Kernel 2: reduce per-tile partials -> mean, rsig. Fixed order.
// ---------------------------------------------------------------------------
__global__ void stats_reduce_kernel()
{
    int i = blockIdx.x * blockDim.x + threadIdx.x;
    if (i >= N_ * G_) return;
    int n = i / G_, g = i - n * G_;
    float S = 0.f, Q = 0.f;
    for (int hb = 0; hb < HB_; ++hb)
        for (int wbv = 0; wbv < WB_; ++wbv) {
            int tl = (n * HB_ + hb) * WB_ + wbv;
            S += g_ps[tl * G_ + g];
            Q += g_pq[tl * G_ + g];
        }
    const float inv_cnt = 1.f / (float)(4 * OH * OW);
    float mean = S * inv_cnt;
    float var  = Q * inv_cnt - mean * mean;
    g_mean[i] = mean;
    g_rsig[i] = rsqrtf(var + 1e-5f);
}

// ---------------------------------------------------------------------------
// Kernel 3: affine on pre-selected extreme, clamp.
// ---------------------------------------------------------------------------
__global__ __launch_bounds__(256) void finalize_pool_kernel(
    const float* __restrict__ gnw,
    const float* __restrict__ gnb,
    const float* __restrict__ scale,
    float* __restrict__ out)
{
    const int total = N_ * COUT * OPH * OPW;
    int idx = blockIdx.x * 256 + threadIdx.x;
    if (idx >= total) return;

    int t = idx / (OPH * OPW);
    int c = t % COUT;
    int n = t / COUT;

    int gi = n * G_ + (c >> 2);
    float mean = g_mean[gi];
    float rsig = g_rsig[gi];
    float a = rsig * gnw[c] * scale[c];
    float b = (gnb[c] - mean * rsig * gnw[c]) * scale[c];

    float v = fmaf(g_ext[idx], a, b);
    out[idx] = fminf(fmaxf(v, 0.f), 1.f);
}

// ---------------------------------------------------------------------------
extern "C" void kernel_launch(void* const* d_in, const int* in_sizes, int n_in,
                              void* d_out, int out_size)
{
    const float* x     = (const float*)d_in[0];
    const float* cw    = (const float*)d_in[1];
    const float* cb    = (const float*)d_in[2];
    const float* gnw   = (const float*)d_in[3];
    const float* gnb   = (const float*)d_in[4];
    const float* scale = (const float*)d_in[5];
    float* out = (float*)d_out;

    static bool attr_set = false;
    if (!attr_set) {
        cudaFuncSetAttribute(conv_mma_kernel,
                             cudaFuncAttributeMaxDynamicSharedMemorySize, SMEM_TOTAL);
        attr_set = true;
    }

    bprep_kernel<<<9, 256>>>(cw, gnw, scale);

    dim3 grid(WB_, HB_, N_);
    conv_mma_kernel<<<grid, 256, SMEM_TOTAL>>>(x, cb);

    stats_reduce_kernel<<<(N_ * G_ + 255) / 256, 256>>>();

    const int total = N_ * COUT * OPH * OPW;
    finalize_pool_kernel<<<(total + 255) / 256, 256>>>(gnw, gnb, scale, out);
}

// round 9
// speedup vs baseline: 3.6448x; 1.1549x over previous
#include <cuda_runtime.h>
#include <cuda_fp16.h>
#include <cstdint>
#include <cstddef>

#define N_    128
#define CIN   8
#define HIN   128
#define WIN   128
#define COUT  64
#define OH    126
#define OW    126
#define G_    16
#define OPH   31
#define OPW   31

#define HB_   16
#define WB_   4
#define NTILES (N_ * HB_ * WB_)

// ---- smem layout (bytes) ----
// phase 1: sB2h [0,10240), sX [10240,23200)  (sX = 9 ic planes x 10 x 36, plane 8 = zeros)
// phase 2: sO [0,75776) (256 px x 74 floats), aliases phase-1 regions
#define OFF_B2   0
#define OFF_X    10240
#define OFF_OUT  0
#define OFF_CB   75776
#define OFF_RED  76032
#define OFF_SG   78080
#define SMEM_TOTAL 78336

#define SO 74    // s_out px stride

// ---- device scratch ----
// B pairs: [oc][kk(5)][r4(4)] uint2 = (half2(k0,k0+1), half2(k0+8,k0+9)), k0=16kk+2r4
__device__ uint2 g_B2h[64 * 20];
__device__ float g_sgn[64];
__device__ float g_ext[(size_t)N_ * COUT * OPH * OPW];
__device__ float g_ps[NTILES * G_];
__device__ float g_pq[NTILES * G_];
__device__ float g_mean[N_ * G_];
__device__ float g_rsig[N_ * G_];

__device__ __forceinline__ uint32_t pack_h2(float lo, float hi) {
    uint32_t r;  // cvt.rn.f16x2.f32 d, a, b -> d.hi = cvt(a), d.lo = cvt(b)
    asm("cvt.rn.f16x2.f32 %0, %1, %2;" : "=r"(r) : "f"(hi), "f"(lo));
    return r;
}

__device__ __forceinline__ void mma16(float* c, const uint32_t* a, uint32_t b0, uint32_t b1) {
    asm volatile(
        "mma.sync.aligned.m16n8k16.row.col.f32.f16.f16.f32 "
        "{%0,%1,%2,%3}, {%4,%5,%6,%7}, {%8,%9}, {%0,%1,%2,%3};"
        : "+f"(c[0]), "+f"(c[1]), "+f"(c[2]), "+f"(c[3])
        : "r"(a[0]), "r"(a[1]), "r"(a[2]), "r"(a[3]), "r"(b0), "r"(b1));
}

// k (< 80) -> sX offset ic*360 + kh*36 + kw   (sX layout [ic(9)][10][36])
__device__ __forceinline__ int koff(int k) {
    int ic = (k * 57) >> 9;        // k/9 for k < 81
    int r  = k - 9 * ic;
    int kh = (r * 11) >> 5;        // r/3 for r < 9
    int kw = r - 3 * kh;
    return ic * 360 + kh * 36 + kw;
}

// ---------------------------------------------------------------------------
// Kernel 0: weights -> fp16 pairs keyed [oc][kk][r4]; sign of a per oc.
// ---------------------------------------------------------------------------
__global__ void bprep_kernel(const float* __restrict__ cw,
                             const float* __restrict__ gnw,
                             const float* __restrict__ scale)
{
    int e = blockIdx.x * blockDim.x + threadIdx.x;
    if (e < 64) g_sgn[e] = (gnw[e] * scale[e] > 0.f) ? 1.f : -1.f;
    if (e >= 64 * 20) return;
    int oc = e / 20, rem = e - (e / 20) * 20;
    int kk = rem >> 2, r4 = rem & 3;
    int k0 = 16 * kk + 2 * r4;

    float w[4];
    #pragma unroll
    for (int i = 0; i < 4; ++i) {
        int k = k0 + ((i >> 1) << 3) + (i & 1);   // k0, k0+1, k0+8, k0+9
        float v = 0.f;
        if (k < 72) {
            int ic = k / 9, r = k % 9;
            v = cw[((oc * 8 + ic) * 3 + r / 3) * 3 + (r % 3)];
        }
        w[i] = v;
    }
    __half2 p0 = __floats2half2_rn(w[0], w[1]);   // lo = k0, hi = k0+1
    __half2 p1 = __floats2half2_rn(w[2], w[3]);
    uint2 out;
    out.x = *(uint32_t*)&p0;
    out.y = *(uint32_t*)&p1;
    g_B2h[e] = out;
}

// ---------------------------------------------------------------------------
// Kernel 1: implicit-GEMM conv (mma.sync fp16 m16n8k16, f32 accum) + bias +
// fused pool extreme + per-group partials. 256 threads, grid (wb, hb, n).
// Lane->pixel permutation: tile row q -> px 4q+2t+h.
// ---------------------------------------------------------------------------
__global__ __launch_bounds__(256, 2)
void conv_mma_kernel(const float* __restrict__ x, const float* __restrict__ cb)
{
    extern __shared__ char smem[];
    uint2*  sB2 = (uint2*)(smem + OFF_B2);    // [oc][kk][r4], stride 20/oc
    float*  sX  = (float*)(smem + OFF_X);     // [9][10][36], plane 8 zeroed
    float*  sO  = (float*)(smem + OFF_OUT);   // [256][SO]
    float*  sCb = (float*)(smem + OFF_CB);
    float*  sRd = (float*)(smem + OFF_RED);
    float*  sSg = (float*)(smem + OFF_SG);

    const int tid  = threadIdx.x;
    const int wid  = tid >> 5;
    const int lane = tid & 31;
    const int wb = blockIdx.x, hb = blockIdx.y, n = blockIdx.z;
    const int h0 = hb * 8, w0 = wb * 32;

    const int q  = lane >> 2;
    const int r4 = lane & 3;

    // copy packed weights: g_B2h = 10240 B = 640 float4  (R8 bug: copied 320)
    {
        const float4* src = (const float4*)g_B2h;
        float4* dst = (float4*)sB2;
        #pragma unroll 3
        for (int i = tid; i < 640; i += 256) dst[i] = src[i];
    }
    if (tid < 64) { sCb[tid] = cb[tid]; sSg[tid] = g_sgn[tid]; }

    // stage x: 9 ic-planes x 10 rows x 36 cols (plane 8 = zeros)
    for (int idx = tid; idx < 810; idx += 256) {
        int ic  = idx / 90, rem = idx - ic * 90;
        int hr  = rem / 9,  c4  = rem - hr * 9;
        int h = h0 + hr, gw = w0 + c4 * 4;
        float4 v = make_float4(0.f, 0.f, 0.f, 0.f);
        if (ic < CIN && h < HIN) {
            const float* rp = x + (((size_t)n * CIN + ic) * HIN + h) * WIN;
            if (gw + 3 < WIN) v = *(const float4*)(rp + gw);
            else {
                if (gw + 0 < WIN) v.x = rp[gw + 0];
                if (gw + 1 < WIN) v.y = rp[gw + 1];
                if (gw + 2 < WIN) v.z = rp[gw + 2];
            }
        }
        *(float4*)(sX + (ic * 10 + hr) * 36 + c4 * 4) = v;
    }
    __syncthreads();

    const int P = wid * 36 + 4 * q;

    float acc[2][8][4];
    #pragma unroll
    for (int t = 0; t < 2; ++t)
        #pragma unroll
        for (int j = 0; j < 8; ++j)
            #pragma unroll
            for (int u = 0; u < 4; ++u) acc[t][j][u] = 0.f;

    // ---- MMA mainloop: 5 k16-steps (K padded 72 -> 80) ----
    #pragma unroll
    for (int kk = 0; kk < 5; ++kk) {
        const int k0 = 16 * kk + 2 * r4;
        const float* p00 = sX + koff(k0)     + P;
        const float* p01 = sX + koff(k0 + 1) + P;
        const float* p10 = sX + koff(k0 + 8) + P;
        const float* p11 = sX + koff(k0 + 9) + P;

        uint32_t a[2][4];
        #pragma unroll
        for (int t = 0; t < 2; ++t) {
            const int c = 2 * t;
            a[t][0] = pack_h2(p00[c],     p01[c]);       // row q   : k0, k0+1
            a[t][1] = pack_h2(p00[c + 1], p01[c + 1]);   // row q+8
            a[t][2] = pack_h2(p10[c],     p11[c]);       // row q   : k0+8, k0+9
            a[t][3] = pack_h2(p10[c + 1], p11[c + 1]);   // row q+8
        }
        const uint2* bp = sB2 + q * 20 + kk * 4 + r4;
        #pragma unroll
        for (int j = 0; j < 8; ++j) {
            uint2 bv = bp[j * 160];                      // (8j+q)*20
            mma16(acc[0][j], a[0], bv.x, bv.y);
            mma16(acc[1][j], a[1], bv.x, bv.y);
        }
    }
    __syncthreads();   // sB2/sX dead; region becomes s_out

    // ---- epilogue: +bias, zero invalid, paired STS.64 -> sO[px][oc] ----
    const bool hok = (h0 + wid) < OH;
    #pragma unroll
    for (int t = 0; t < 2; ++t) {
        const int ww0 = 4 * q + 2 * t;
        const int px  = (wid << 5) + ww0;
        const bool v0 = hok && (w0 + ww0 < OW);
        const bool v1 = hok && (w0 + ww0 + 1 < OW);
        #pragma unroll
        for (int j = 0; j < 8; ++j) {
            const int oc = (j << 3) + (r4 << 1);
            float2 bc = *(float2*)(sCb + oc);
            float2 e0, e1;
            e0.x = v0 ? acc[t][j][0] + bc.x : 0.f;   // row q   -> px
            e0.y = v0 ? acc[t][j][1] + bc.y : 0.f;
            e1.x = v1 ? acc[t][j][2] + bc.x : 0.f;   // row q+8 -> px+1
            e1.y = v1 ? acc[t][j][3] + bc.y : 0.f;
            *(float2*)(sO + px * SO + oc)       = e0;
            *(float2*)(sO + (px + 1) * SO + oc) = e1;
        }
    }
    __syncthreads();

    // ---- stats: column scan, 4 partials per oc, fixed order ----
    {
        const int oc = tid & 63, part = tid >> 6;
        const float* p = sO + part * 64 * SO + oc;
        float s = 0.f, qq = 0.f;
        #pragma unroll 8
        for (int i = 0; i < 64; ++i) {
            float v = p[i * SO];
            s += v; qq = fmaf(v, v, qq);
        }
        sRd[tid] = s; sRd[256 + tid] = qq;
    }
    __syncthreads();

    const int tile = (n * HB_ + hb) * WB_ + wb;
    if (tid < 16) {
        float S = 0.f, Q = 0.f;
        #pragma unroll
        for (int part = 0; part < 4; ++part)
            #pragma unroll
            for (int c2 = 0; c2 < 4; ++c2) {
                S += sRd[part * 64 + tid * 4 + c2];
                Q += sRd[256 + part * 64 + tid * 4 + c2];
            }
        g_ps[tile * G_ + tid] = S;
        g_pq[tile * G_ + tid] = Q;
    }

    // ---- pool: sign-relevant extreme only ----
    #pragma unroll
    for (int i = 0; i < 4; ++i) {
        const int task = tid + (i << 8);
        const int oc = task & 63, j = (task >> 6) & 7, prl = task >> 9;
        const int pw = wb * 8 + j, pr = hb * 2 + prl;
        if (pw < OPW && pr < OPH) {
            float mx = -3.4e38f, mn = 3.4e38f;
            #pragma unroll
            for (int a2 = 0; a2 < 4; ++a2)
                #pragma unroll
                for (int b2 = 0; b2 < 4; ++b2) {
                    float v = sO[((prl * 4 + a2) * 32 + j * 4 + b2) * SO + oc];
                    mx = fmaxf(mx, v); mn = fminf(mn, v);
                }
            size_t o = ((size_t)(n * COUT + oc) * OPH + pr) * OPW + pw;
            g_ext[o] = (sSg[oc] > 0.f) ? mx : mn;
        }
    }
}

// ---------------------------------------------------------------------------
// Kernel 2: reduce per-tile partials -> mean, rsig. Fixed order.
// ---------------------------------------------------------------------------
__global__ void stats_reduce_kernel()
{
    int i = blockIdx.x * blockDim.x + threadIdx.x;
    if (i >= N_ * G_) return;
    int n = i / G_, g = i - n * G_;
    float S = 0.f, Q = 0.f;
    for (int hb = 0; hb < HB_; ++hb)
        for (int wbv = 0; wbv < WB_; ++wbv) {
            int tl = (n * HB_ + hb) * WB_ + wbv;
            S += g_ps[tl * G_ + g];
            Q += g_pq[tl * G_ + g];
        }
    const float inv_cnt = 1.f / (float)(4 * OH * OW);
    float mean = S * inv_cnt;
    float var  = Q * inv_cnt - mean * mean;
    g_mean[i] = mean;
    g_rsig[i] = rsqrtf(var + 1e-5f);
}

// ---------------------------------------------------------------------------
// Kernel 3: affine on pre-selected extreme, clamp. 4 px / thread (float4).
// ---------------------------------------------------------------------------
__global__ __launch_bounds__(256) void finalize_pool_kernel(
    const float* __restrict__ gnw,
    const float* __restrict__ gnb,
    const float* __restrict__ scale,
    float* __restrict__ out)
{
    const int total4 = (N_ * COUT * OPH * OPW) >> 2;   // divisible by 4
    int t4 = blockIdx.x * 256 + threadIdx.x;
    if (t4 >= total4) return;
    int idx = t4 << 2;

    float4 e = *(const float4*)(g_ext + idx);
    float r[4] = {e.x, e.y, e.z, e.w};
    float4 o;
    float* op = &o.x;

    #pragma unroll
    for (int i = 0; i < 4; ++i) {
        int id = idx + i;
        int t = id / (OPH * OPW);
        int c = t % COUT;
        int n = t / COUT;
        int gi = n * G_ + (c >> 2);
        float mean = g_mean[gi];
        float rsig = g_rsig[gi];
        float a = rsig * gnw[c] * scale[c];
        float b = (gnb[c] - mean * rsig * gnw[c]) * scale[c];
        op[i] = fminf(fmaxf(fmaf(r[i], a, b), 0.f), 1.f);
    }
    *(float4*)(out + idx) = o;
}

// ---------------------------------------------------------------------------
extern "C" void kernel_launch(void* const* d_in, const int* in_sizes, int n_in,
                              void* d_out, int out_size)
{
    const float* x     = (const float*)d_in[0];
    const float* cw    = (const float*)d_in[1];
    const float* cb    = (const float*)d_in[2];
    const float* gnw   = (const float*)d_in[3];
    const float* gnb   = (const float*)d_in[4];
    const float* scale = (const float*)d_in[5];
    float* out = (float*)d_out;

    static bool attr_set = false;
    if (!attr_set) {
        cudaFuncSetAttribute(conv_mma_kernel,
                             cudaFuncAttributeMaxDynamicSharedMemorySize, SMEM_TOTAL);
        attr_set = true;
    }

    bprep_kernel<<<6, 256>>>(cw, gnw, scale);

    dim3 grid(WB_, HB_, N_);
    conv_mma_kernel<<<grid, 256, SMEM_TOTAL>>>(x, cb);

    stats_reduce_kernel<<<(N_ * G_ + 255) / 256, 256>>>();

    const int total4 = (N_ * COUT * OPH * OPW) / 4;
    finalize_pool_kernel<<<(total4 + 255) / 256, 256>>>(gnw, gnb, scale, out);
}